// round 7
// baseline (speedup 1.0000x reference)
#include <cuda_runtime.h>
#include <cuda_bf16.h>
#include <cstdint>

// Problem constants (z: [32,64,64,64] f32, codebook: [1024,64] f32)
#define BB      32
#define CC      64
#define HWN     4096
#define NQ      (BB * HWN)        // 131072 queries
#define KCODES  1024
#define MTILE   128               // queries per CTA
#define NCHUNK  128               // codes staged per smem chunk
#define THREADS 128
#define NBLOCKS (NQ / MTILE)      // 1024
#define ZELEMS  (BB * CC * HWN)
#define EPS_SCREEN 0.75f          // hi-only screening window (2x worst dot err + margin)
#define PADW    72                // row stride (bf16): 144B = 9*16B, ldmatrix conflict-free

// dynamic smem layout (bytes) — B region cycles: A-hi (transient) -> B chunks -> cand
#define OFF_B    0                             // 128 x 72 bf16 = 18432
#define OFF_SCN  18432                         // 128 floats
#define OFF_WERR 18944                         // 4 floats
#define SMEM_TOTAL 19008

__device__ float g_cnorm[KCODES];
__device__ float g_partials[NBLOCKS];
// prepped codebook: bf16 of (-2c), rows padded to PADW
__device__ __align__(16) __nv_bfloat16 g_cbimg[KCODES * PADW];

// ---------------------------------------------------------------------------
__device__ __forceinline__ uint32_t smem_to_u32(const void* p) {
    uint32_t a;
    asm("{ .reg .u64 t; cvta.to.shared.u64 t, %1; cvt.u32.u64 %0, t; }"
        : "=r"(a) : "l"(p));
    return a;
}

#define LDSM_X4(r, addr) \
    asm volatile("ldmatrix.sync.aligned.m8n8.x4.shared.b16 {%0,%1,%2,%3}, [%4];" \
        : "=r"((r)[0]), "=r"((r)[1]), "=r"((r)[2]), "=r"((r)[3]) : "r"(addr))

#define MMA16816(d, a, b) \
    asm volatile("mma.sync.aligned.m16n8k16.row.col.f32.bf16.bf16.f32 " \
        "{%0,%1,%2,%3}, {%4,%5,%6,%7}, {%8,%9}, {%0,%1,%2,%3};" \
        : "+f"((d)[0]), "+f"((d)[1]), "+f"((d)[2]), "+f"((d)[3]) \
        : "r"((a)[0]), "r"((a)[1]), "r"((a)[2]), "r"((a)[3]), \
          "r"((b)[0]), "r"((b)[1]))

__device__ __forceinline__ void top4_insert(float s, int idx, float* ts, int* ti) {
    if (s < ts[3]) {
        if (s < ts[0]) {
            ts[3]=ts[2]; ti[3]=ti[2]; ts[2]=ts[1]; ti[2]=ti[1];
            ts[1]=ts[0]; ti[1]=ti[0]; ts[0]=s; ti[0]=idx;
        } else if (s < ts[1]) {
            ts[3]=ts[2]; ti[3]=ti[2]; ts[2]=ts[1]; ti[2]=ti[1]; ts[1]=s; ti[1]=idx;
        } else if (s < ts[2]) {
            ts[3]=ts[2]; ti[3]=ti[2]; ts[2]=s; ti[2]=idx;
        } else {
            ts[3]=s; ti[3]=idx;
        }
    }
}

// ---------------------------------------------------------------------------
// Kernel 0: prep — cn = ||c||^2 (fp32 exact), bf16 image of (-2c)
// ---------------------------------------------------------------------------
__global__ void prep_kernel(const float* __restrict__ cb) {
    int k = blockIdx.x * blockDim.x + threadIdx.x;
    if (k >= KCODES) return;
    const float2* r = reinterpret_cast<const float2*>(cb + (size_t)k * CC);
    __nv_bfloat16* row = g_cbimg + (size_t)k * PADW;
    float cn = 0.f;
#pragma unroll
    for (int c = 0; c < CC / 2; c++) {
        float2 v = __ldg(r + c);
        cn = fmaf(v.x, v.x, cn);
        cn = fmaf(v.y, v.y, cn);
        __nv_bfloat162 hp;
        hp.x = __float2bfloat16_rn(-2.f * v.x);
        hp.y = __float2bfloat16_rn(-2.f * v.y);
        *reinterpret_cast<__nv_bfloat162*>(row + 2 * c) = hp;
    }
    g_cnorm[k] = cn;
}

// exact fp64 squared distance (refinement path)
__device__ double dist2_f64(const float* __restrict__ zp,
                            const float* __restrict__ cb, int idx) {
    const float* cp = cb + (size_t)idx * CC;
    double d = 0.0;
#pragma unroll
    for (int c = 0; c < CC; c++) {
        double df = (double)zp[(size_t)c * HWN] - (double)cp[c];
        d = fma(df, df, d);
    }
    return d;
}

// ---------------------------------------------------------------------------
// Kernel 1: HMMA VQ — hi-only bf16 screen + exact window refinement
// ---------------------------------------------------------------------------
extern __shared__ unsigned char dynsmem[];

__global__ __launch_bounds__(THREADS, 4)
void vq_kernel(const float* __restrict__ z,
               const float* __restrict__ cb,
               float* __restrict__ out) {
    const int tid = threadIdx.x;
    const int w = tid >> 5;
    const int l = tid & 31;
    const uint32_t sb = smem_to_u32(dynsmem);

    __nv_bfloat16* Ahi = reinterpret_cast<__nv_bfloat16*>(dynsmem + OFF_B); // transient
    float* scn  = reinterpret_cast<float*>(dynsmem + OFF_SCN);
    float* werr = reinterpret_cast<float*>(dynsmem + OFF_WERR);
    float2* cand = reinterpret_cast<float2*>(dynsmem + OFF_B);  // reused post-loop

    const int q = blockIdx.x * MTILE + tid;
    const int b = q >> 12;
    const float* zp = z + (size_t)b * CC * HWN + (q & (HWN - 1));

    // --- A tile: z query -> bf16 hi, staged transiently in B region ---
#pragma unroll
    for (int c = 0; c < CC; c++)
        Ahi[tid * PADW + c] = __float2bfloat16_rn(zp[(size_t)c * HWN]);
    __syncthreads();

    // --- hoist A fragments: 4 k-slices x (a0[4], a1[4]) = 32 regs ---
    const int rowA = w * 32 + (l & 15);
    const int colA = ((l >> 4) & 1) * 8;
    uint32_t afr[32];
#pragma unroll
    for (int fi = 0; fi < 4; fi++) {
        LDSM_X4(afr + fi * 8,
                sb + OFF_B + (uint32_t)((rowA)      * PADW + colA + fi * 16) * 2);
        LDSM_X4(afr + fi * 8 + 4,
                sb + OFF_B + (uint32_t)((rowA + 16) * PADW + colA + fi * 16) * 2);
    }

    // per-thread top-4 over 4 query-slots (16 disjoint code-subsets)
    float ts[16];
    int   ti[16];
#pragma unroll
    for (int i = 0; i < 16; i++) { ts[i] = 3.4e38f; ti[i] = 0x7fffffff; }

    const int rowB = ((l >> 4) & 1) * 8 + (l & 7);
    const int colB = ((l >> 3) & 1) * 8;

#pragma unroll 1
    for (int ch = 0; ch < KCODES / NCHUNK; ch++) {
        __syncthreads();  // prev chunk fully consumed (B region reusable)
        // stage code chunk into B region (18432 B = 1152 int4)
        {
            const int4* src = reinterpret_cast<const int4*>(g_cbimg + (size_t)ch * NCHUNK * PADW);
            int4* dst = reinterpret_cast<int4*>(dynsmem + OFF_B);
#pragma unroll
            for (int i = 0; i < 9; i++) dst[tid + i * THREADS] = src[tid + i * THREADS];
            scn[tid] = g_cnorm[ch * NCHUNK + tid];
        }
        __syncthreads();

#pragma unroll 1
        for (int nsub = 0; nsub < 4; nsub++) {
            // accum init: d[(mt*4+nt)*4+e] = cn[n(e)]
            float d[32];
#pragma unroll
            for (int nt = 0; nt < 4; nt++) {
                float cn0 = scn[nsub * 32 + nt * 8 + 2 * (l & 3)];
                float cn1 = scn[nsub * 32 + nt * 8 + 2 * (l & 3) + 1];
#pragma unroll
                for (int mt = 0; mt < 2; mt++) {
                    d[(mt * 4 + nt) * 4 + 0] = cn0;
                    d[(mt * 4 + nt) * 4 + 1] = cn1;
                    d[(mt * 4 + nt) * 4 + 2] = cn0;
                    d[(mt * 4 + nt) * 4 + 3] = cn1;
                }
            }

            const uint32_t bbase = sb + OFF_B +
                (uint32_t)((nsub * 32 + rowB) * PADW + colB) * 2;

            // hi-only screen: zh * bh (4 k-steps)
#pragma unroll
            for (int s = 0; s < 4; s++) {
                uint32_t bf[8];
                LDSM_X4(bf,     bbase + (uint32_t)(s * 16) * 2);
                LDSM_X4(bf + 4, bbase + (uint32_t)(16 * PADW + s * 16) * 2);
                const uint32_t* a0 = afr + s * 8;
#pragma unroll
                for (int nt = 0; nt < 4; nt++) {
                    MMA16816(d + (0 * 4 + nt) * 4, a0,     bf + nt * 2);
                    MMA16816(d + (1 * 4 + nt) * 4, a0 + 4, bf + nt * 2);
                }
            }

            // top-4 update: slot = mt*2 + (e>>1)
#pragma unroll
            for (int mt = 0; mt < 2; mt++)
#pragma unroll
                for (int nt = 0; nt < 4; nt++)
#pragma unroll
                    for (int e = 0; e < 4; e++) {
                        float s = d[(mt * 4 + nt) * 4 + e];
                        int idx = ch * NCHUNK + nsub * 32 + nt * 8 + 2 * (l & 3) + (e & 1);
                        int slot = mt * 2 + (e >> 1);
                        top4_insert(s, idx, ts + slot * 4, ti + slot * 4);
                    }
        }
    }

    // --- merge candidates via smem (stride 17 float2; reuses B region) ---
    __syncthreads();
#pragma unroll
    for (int s = 0; s < 4; s++) {
        int mt = s >> 1, half = s & 1;
        int ql = w * 32 + mt * 16 + half * 8 + (l >> 2);
#pragma unroll
        for (int e = 0; e < 4; e++)
            cand[ql * 17 + (l & 3) * 4 + e] =
                make_float2(ts[s * 4 + e], __int_as_float(ti[s * 4 + e]));
    }
    __syncthreads();

    // --- per-query (thread = query): window + fp64 refinement ---
    float cs[16]; int ci[16];
#pragma unroll
    for (int j = 0; j < 16; j++) {
        float2 v = cand[tid * 17 + j];
        cs[j] = v.x; ci[j] = __float_as_int(v.y);
    }
    float smin = cs[0];
#pragma unroll
    for (int j = 1; j < 16; j++) smin = fminf(smin, cs[j]);

    int nwin = 0, lone = 0;
#pragma unroll
    for (int j = 0; j < 16; j++)
        if (cs[j] < smin + EPS_SCREEN) { nwin++; lone = j; }

    int bidx;
    if (nwin == 1) {
        bidx = ci[lone];
    } else {
        double bd = 1e300;
        int bi = 0x7fffffff;
#pragma unroll
        for (int j = 0; j < 16; j++) {
            if (cs[j] < smin + EPS_SCREEN) {
                double dd = dist2_f64(zp, cb, ci[j]);
                if (dd < bd || (dd == bd && ci[j] < bi)) { bd = dd; bi = ci[j]; }
            }
        }
        bidx = bi;
    }

    // --- write z_q + squared-error partial (coalesced: threads = consecutive n) ---
    float err = 0.f;
    {
        const float* cv = cb + (size_t)bidx * CC;
        float* op = out + (size_t)b * CC * HWN + (q & (HWN - 1));
#pragma unroll
        for (int c = 0; c < CC; c++) {
            float v = __ldg(cv + c);
            float zv = zp[(size_t)c * HWN];
            op[(size_t)c * HWN] = v;
            float df = v - zv;
            err = fmaf(df, df, err);
        }
    }
#pragma unroll
    for (int o = 16; o > 0; o >>= 1)
        err += __shfl_down_sync(0xFFFFFFFFu, err, o);
    if (l == 0) werr[w] = err;
    __syncthreads();
    if (tid == 0)
        g_partials[blockIdx.x] = werr[0] + werr[1] + werr[2] + werr[3];
}

// ---------------------------------------------------------------------------
// Kernel 2: deterministic loss = 1.25 * mean((z_q - z)^2)
// ---------------------------------------------------------------------------
__global__ void loss_kernel(float* __restrict__ loss_out) {
    __shared__ double s[512];
    s[threadIdx.x] = (double)g_partials[threadIdx.x] +
                     (double)g_partials[threadIdx.x + 512];
    __syncthreads();
#pragma unroll
    for (int st = 256; st > 0; st >>= 1) {
        if (threadIdx.x < st) s[threadIdx.x] += s[threadIdx.x + st];
        __syncthreads();
    }
    if (threadIdx.x == 0)
        loss_out[0] = (float)(1.25 * s[0] / (double)ZELEMS);
}

// ---------------------------------------------------------------------------
extern "C" void kernel_launch(void* const* d_in, const int* in_sizes, int n_in,
                              void* d_out, int out_size) {
    const float* z  = (const float*)d_in[0];
    const float* cb = (const float*)d_in[1];
    float* out = (float*)d_out;

    cudaFuncSetAttribute(vq_kernel, cudaFuncAttributeMaxDynamicSharedMemorySize,
                         SMEM_TOTAL);

    prep_kernel<<<8, 128>>>(cb);
    vq_kernel<<<NBLOCKS, THREADS, SMEM_TOTAL>>>(z, cb, out);
    if (out_size > ZELEMS)
        loss_kernel<<<1, 512>>>(out + ZELEMS);
}

// round 8
// speedup vs baseline: 2.1504x; 2.1504x over previous
#include <cuda_runtime.h>
#include <cuda_bf16.h>
#include <cstdint>

// Problem constants (z: [32,64,64,64] f32, codebook: [1024,64] f32)
#define BB      32
#define CC      64
#define HWN     4096
#define NQ      (BB * HWN)        // 131072 queries
#define KCODES  1024
#define MTILE   128               // queries per CTA
#define NCHUNK  128               // codes staged per smem chunk
#define NCH     (KCODES / NCHUNK) // 8
#define THREADS 128
#define NBLOCKS (NQ / MTILE)      // 1024
#define ZELEMS  (BB * CC * HWN)
#define EPS_SCREEN 0.75f          // hi-only screening window (6-sigma + margin)
#define EPS_TIE    5e-3f          // fp32 diff-form tie gate (>2x fp32 error bound)
#define PADW    72                // row stride (bf16): 144B = 9*16B, ldmatrix conflict-free

#define BBYTES  (NCHUNK * PADW * 2)            // 18432 per chunk image
// dynamic smem: two staging buffers {B, scn}, then small scratch.
// buf0.B doubles as: A-hi staging (prologue) and candidate buffer (epilogue).
#define OFF_BUF0   0
#define OFF_BUF1   (BBYTES + 512)              // 18944
#define OFF_SCN0   BBYTES                      // buf0.scn
#define OFF_SCN1   (OFF_BUF1 + BBYTES)         // buf1.scn
#define OFF_WERR   (OFF_BUF1 + BBYTES + 512)   // 37888
#define SMEM_TOTAL (OFF_WERR + 64)             // 37952

__device__ float g_cnorm[KCODES];
__device__ float g_partials[NBLOCKS];
// prepped codebook: bf16 of (-2c), rows padded to PADW
__device__ __align__(16) __nv_bfloat16 g_cbimg[KCODES * PADW];

// ---------------------------------------------------------------------------
__device__ __forceinline__ uint32_t smem_to_u32(const void* p) {
    uint32_t a;
    asm("{ .reg .u64 t; cvta.to.shared.u64 t, %1; cvt.u32.u64 %0, t; }"
        : "=r"(a) : "l"(p));
    return a;
}

#define LDSM_X4(r, addr) \
    asm volatile("ldmatrix.sync.aligned.m8n8.x4.shared.b16 {%0,%1,%2,%3}, [%4];" \
        : "=r"((r)[0]), "=r"((r)[1]), "=r"((r)[2]), "=r"((r)[3]) : "r"(addr))

#define MMA16816(d, a, b) \
    asm volatile("mma.sync.aligned.m16n8k16.row.col.f32.bf16.bf16.f32 " \
        "{%0,%1,%2,%3}, {%4,%5,%6,%7}, {%8,%9}, {%0,%1,%2,%3};" \
        : "+f"((d)[0]), "+f"((d)[1]), "+f"((d)[2]), "+f"((d)[3]) \
        : "r"((a)[0]), "r"((a)[1]), "r"((a)[2]), "r"((a)[3]), \
          "r"((b)[0]), "r"((b)[1]))

#define CP_ASYNC16(sm, gp) \
    asm volatile("cp.async.cg.shared.global [%0], [%1], 16;" :: "r"(sm), "l"(gp))
#define CP_ASYNC4(sm, gp) \
    asm volatile("cp.async.ca.shared.global [%0], [%1], 4;" :: "r"(sm), "l"(gp))
#define CP_COMMIT() asm volatile("cp.async.commit_group;" ::: "memory")
#define CP_WAIT1()  asm volatile("cp.async.wait_group 1;" ::: "memory")

__device__ __forceinline__ void top4_insert(float s, int idx, float* ts, int* ti) {
    if (s < ts[3]) {
        if (s < ts[0]) {
            ts[3]=ts[2]; ti[3]=ti[2]; ts[2]=ts[1]; ti[2]=ti[1];
            ts[1]=ts[0]; ti[1]=ti[0]; ts[0]=s; ti[0]=idx;
        } else if (s < ts[1]) {
            ts[3]=ts[2]; ti[3]=ti[2]; ts[2]=ts[1]; ti[2]=ti[1]; ts[1]=s; ti[1]=idx;
        } else if (s < ts[2]) {
            ts[3]=ts[2]; ti[3]=ti[2]; ts[2]=s; ti[2]=idx;
        } else {
            ts[3]=s; ti[3]=idx;
        }
    }
}

// ---------------------------------------------------------------------------
// Kernel 0: prep — cn = ||c||^2 (fp32 exact), bf16 image of (-2c)
// ---------------------------------------------------------------------------
__global__ void prep_kernel(const float* __restrict__ cb) {
    int k = blockIdx.x * blockDim.x + threadIdx.x;
    if (k >= KCODES) return;
    const float2* r = reinterpret_cast<const float2*>(cb + (size_t)k * CC);
    __nv_bfloat16* row = g_cbimg + (size_t)k * PADW;
    float cn = 0.f;
#pragma unroll
    for (int c = 0; c < CC / 2; c++) {
        float2 v = __ldg(r + c);
        cn = fmaf(v.x, v.x, cn);
        cn = fmaf(v.y, v.y, cn);
        __nv_bfloat162 hp;
        hp.x = __float2bfloat16_rn(-2.f * v.x);
        hp.y = __float2bfloat16_rn(-2.f * v.y);
        *reinterpret_cast<__nv_bfloat162*>(row + 2 * c) = hp;
    }
    g_cnorm[k] = cn;
}

// fp32 difference-form squared distance (tier-1 refinement; well-conditioned)
__device__ __forceinline__ float dist2_f32(const float* __restrict__ zp,
                                           const float* __restrict__ cb, int idx) {
    const float* cp = cb + (size_t)idx * CC;
    float d = 0.f;
#pragma unroll
    for (int c = 0; c < CC; c++) {
        float df = zp[(size_t)c * HWN] - __ldg(cp + c);
        d = fmaf(df, df, d);
    }
    return d;
}

// fp64 exact squared distance (tier-2, rare)
__device__ double dist2_f64(const float* __restrict__ zp,
                            const float* __restrict__ cb, int idx) {
    const float* cp = cb + (size_t)idx * CC;
    double d = 0.0;
#pragma unroll
    for (int c = 0; c < CC; c++) {
        double df = (double)zp[(size_t)c * HWN] - (double)__ldg(cp + c);
        d = fma(df, df, d);
    }
    return d;
}

// ---------------------------------------------------------------------------
// Kernel 1: HMMA VQ — hi-only bf16 screen + two-tier exact refinement
// ---------------------------------------------------------------------------
extern __shared__ unsigned char dynsmem[];

__global__ __launch_bounds__(THREADS, 4)
void vq_kernel(const float* __restrict__ z,
               const float* __restrict__ cb,
               float* __restrict__ out) {
    const int tid = threadIdx.x;
    const int w = tid >> 5;
    const int l = tid & 31;
    const uint32_t sb = smem_to_u32(dynsmem);

    __nv_bfloat16* Ahi = reinterpret_cast<__nv_bfloat16*>(dynsmem + OFF_BUF0);
    float* werr = reinterpret_cast<float*>(dynsmem + OFF_WERR);
    float2* cand = reinterpret_cast<float2*>(dynsmem + OFF_BUF0);  // post-loop

    const int q = blockIdx.x * MTILE + tid;
    const int b = q >> 12;
    const float* zp = z + (size_t)b * CC * HWN + (q & (HWN - 1));

    // --- A tile: z query -> bf16 hi, staged transiently in buf0.B ---
#pragma unroll
    for (int c = 0; c < CC; c++)
        Ahi[tid * PADW + c] = __float2bfloat16_rn(zp[(size_t)c * HWN]);
    __syncthreads();

    // --- hoist A fragments: 4 k-slices x (a0[4], a1[4]) = 32 regs ---
    const int rowA = w * 32 + (l & 15);
    const int colA = ((l >> 4) & 1) * 8;
    uint32_t afr[32];
#pragma unroll
    for (int fi = 0; fi < 4; fi++) {
        LDSM_X4(afr + fi * 8,
                sb + OFF_BUF0 + (uint32_t)((rowA)      * PADW + colA + fi * 16) * 2);
        LDSM_X4(afr + fi * 8 + 4,
                sb + OFF_BUF0 + (uint32_t)((rowA + 16) * PADW + colA + fi * 16) * 2);
    }
    __syncthreads();   // buf0 free for prefetch

    // --- prefetch chunks 0,1 via cp.async (double buffer) ---
    const uint32_t bufB[2]   = { sb + OFF_BUF0, sb + OFF_BUF1 };
    const uint32_t bufSCN[2] = { sb + OFF_SCN0, sb + OFF_SCN1 };
#pragma unroll
    for (int p = 0; p < 2; p++) {
        const char* src = reinterpret_cast<const char*>(g_cbimg) + (size_t)p * BBYTES;
#pragma unroll
        for (int i = 0; i < 9; i++)
            CP_ASYNC16(bufB[p] + (uint32_t)(tid + i * THREADS) * 16,
                       src + (size_t)(tid + i * THREADS) * 16);
        CP_ASYNC4(bufSCN[p] + (uint32_t)tid * 4,
                  reinterpret_cast<const char*>(g_cnorm) + (size_t)(p * NCHUNK + tid) * 4);
        CP_COMMIT();
    }

    // per-thread top-4 over 4 query-slots (16 disjoint code-subsets)
    float ts[16];
    int   ti[16];
#pragma unroll
    for (int i = 0; i < 16; i++) { ts[i] = 3.4e38f; ti[i] = 0x7fffffff; }

    const int rowB = ((l >> 4) & 1) * 8 + (l & 7);
    const int colB = ((l >> 3) & 1) * 8;

#pragma unroll 1
    for (int ch = 0; ch < NCH; ch++) {
        CP_WAIT1();           // chunk ch landed (at most 1 newer group pending)
        __syncthreads();

        const uint32_t Bc = bufB[ch & 1];
        const float* scn = reinterpret_cast<const float*>(
            dynsmem + (((ch & 1) ? OFF_SCN1 : OFF_SCN0)));

#pragma unroll 1
        for (int nsub = 0; nsub < 4; nsub++) {
            // accum init: d[(mt*4+nt)*4+e] = cn[n(e)]
            float d[32];
#pragma unroll
            for (int nt = 0; nt < 4; nt++) {
                float cn0 = scn[nsub * 32 + nt * 8 + 2 * (l & 3)];
                float cn1 = scn[nsub * 32 + nt * 8 + 2 * (l & 3) + 1];
#pragma unroll
                for (int mt = 0; mt < 2; mt++) {
                    d[(mt * 4 + nt) * 4 + 0] = cn0;
                    d[(mt * 4 + nt) * 4 + 1] = cn1;
                    d[(mt * 4 + nt) * 4 + 2] = cn0;
                    d[(mt * 4 + nt) * 4 + 3] = cn1;
                }
            }

            const uint32_t bbase = Bc + (uint32_t)((nsub * 32 + rowB) * PADW + colB) * 2;

            // hi-only screen: zh * bh (4 k-steps)
#pragma unroll
            for (int s = 0; s < 4; s++) {
                uint32_t bf[8];
                LDSM_X4(bf,     bbase + (uint32_t)(s * 16) * 2);
                LDSM_X4(bf + 4, bbase + (uint32_t)(16 * PADW + s * 16) * 2);
                const uint32_t* a0 = afr + s * 8;
#pragma unroll
                for (int nt = 0; nt < 4; nt++) {
                    MMA16816(d + (0 * 4 + nt) * 4, a0,     bf + nt * 2);
                    MMA16816(d + (1 * 4 + nt) * 4, a0 + 4, bf + nt * 2);
                }
            }

            // top-4 update: slot = mt*2 + (e>>1)
#pragma unroll
            for (int mt = 0; mt < 2; mt++)
#pragma unroll
                for (int nt = 0; nt < 4; nt++)
#pragma unroll
                    for (int e = 0; e < 4; e++) {
                        float s = d[(mt * 4 + nt) * 4 + e];
                        int idx = ch * NCHUNK + nsub * 32 + nt * 8 + 2 * (l & 3) + (e & 1);
                        int slot = mt * 2 + (e >> 1);
                        top4_insert(s, idx, ts + slot * 4, ti + slot * 4);
                    }
        }

        __syncthreads();      // all warps done with buf[ch&1]
        if (ch + 2 < NCH) {   // prefetch chunk ch+2 into the buffer just freed
            const char* src = reinterpret_cast<const char*>(g_cbimg) + (size_t)(ch + 2) * BBYTES;
#pragma unroll
            for (int i = 0; i < 9; i++)
                CP_ASYNC16(bufB[ch & 1] + (uint32_t)(tid + i * THREADS) * 16,
                           src + (size_t)(tid + i * THREADS) * 16);
            CP_ASYNC4(bufSCN[ch & 1] + (uint32_t)tid * 4,
                      reinterpret_cast<const char*>(g_cnorm) + (size_t)((ch + 2) * NCHUNK + tid) * 4);
            CP_COMMIT();
        }
    }

    // --- merge candidates via smem (stride 17 float2; reuses buf0) ---
#pragma unroll
    for (int s = 0; s < 4; s++) {
        int mt = s >> 1, half = s & 1;
        int ql = w * 32 + mt * 16 + half * 8 + (l >> 2);
#pragma unroll
        for (int e = 0; e < 4; e++)
            cand[ql * 17 + (l & 3) * 4 + e] =
                make_float2(ts[s * 4 + e], __int_as_float(ti[s * 4 + e]));
    }
    __syncthreads();

    // --- per-query (thread = query): window + two-tier refinement ---
    float cs[16]; int ci[16];
#pragma unroll
    for (int j = 0; j < 16; j++) {
        float2 v = cand[tid * 17 + j];
        cs[j] = v.x; ci[j] = __float_as_int(v.y);
    }
    float smin = cs[0];
#pragma unroll
    for (int j = 1; j < 16; j++) smin = fminf(smin, cs[j]);

    int nwin = 0, lone = 0;
#pragma unroll
    for (int j = 0; j < 16; j++)
        if (cs[j] < smin + EPS_SCREEN) { nwin++; lone = j; }

    int bidx;
    if (nwin == 1) {
        bidx = ci[lone];
    } else {
        // tier 1: fp32 difference-form on windowed candidates
        float d32[16];
        float best = 3.4e38f;
        int   bi = 0x7fffffff;
#pragma unroll 1
        for (int j = 0; j < 16; j++) {
            float dd = 3.4e38f;
            if (cs[j] < smin + EPS_SCREEN) {
                dd = dist2_f32(zp, cb, ci[j]);
                if (dd < best || (dd == best && ci[j] < bi)) { best = dd; bi = ci[j]; }
            }
            d32[j] = dd;
        }
        // tier 2: fp64 only if any other candidate within EPS_TIE of fp32 best
        int ntie = 0;
#pragma unroll
        for (int j = 0; j < 16; j++)
            if (d32[j] < best + EPS_TIE) ntie++;
        if (ntie > 1) {
            double bd = 1e300;
            int bi64 = 0x7fffffff;
#pragma unroll 1
            for (int j = 0; j < 16; j++) {
                if (d32[j] < best + EPS_TIE) {
                    double dd = dist2_f64(zp, cb, ci[j]);
                    if (dd < bd || (dd == bd && ci[j] < bi64)) { bd = dd; bi64 = ci[j]; }
                }
            }
            bi = bi64;
        }
        bidx = bi;
    }

    // --- write z_q + squared-error partial (coalesced: threads = consecutive n) ---
    float err = 0.f;
    {
        const float* cv = cb + (size_t)bidx * CC;
        float* op = out + (size_t)b * CC * HWN + (q & (HWN - 1));
#pragma unroll
        for (int c = 0; c < CC; c++) {
            float v = __ldg(cv + c);
            float zv = zp[(size_t)c * HWN];
            op[(size_t)c * HWN] = v;
            float df = v - zv;
            err = fmaf(df, df, err);
        }
    }
#pragma unroll
    for (int o = 16; o > 0; o >>= 1)
        err += __shfl_down_sync(0xFFFFFFFFu, err, o);
    if (l == 0) werr[w] = err;
    __syncthreads();
    if (tid == 0)
        g_partials[blockIdx.x] = werr[0] + werr[1] + werr[2] + werr[3];
}

// ---------------------------------------------------------------------------
// Kernel 2: deterministic loss = 1.25 * mean((z_q - z)^2)
// ---------------------------------------------------------------------------
__global__ void loss_kernel(float* __restrict__ loss_out) {
    __shared__ double s[512];
    s[threadIdx.x] = (double)g_partials[threadIdx.x] +
                     (double)g_partials[threadIdx.x + 512];
    __syncthreads();
#pragma unroll
    for (int st = 256; st > 0; st >>= 1) {
        if (threadIdx.x < st) s[threadIdx.x] += s[threadIdx.x + st];
        __syncthreads();
    }
    if (threadIdx.x == 0)
        loss_out[0] = (float)(1.25 * s[0] / (double)ZELEMS);
}

// ---------------------------------------------------------------------------
extern "C" void kernel_launch(void* const* d_in, const int* in_sizes, int n_in,
                              void* d_out, int out_size) {
    const float* z  = (const float*)d_in[0];
    const float* cb = (const float*)d_in[1];
    float* out = (float*)d_out;

    cudaFuncSetAttribute(vq_kernel, cudaFuncAttributeMaxDynamicSharedMemorySize,
                         SMEM_TOTAL);

    prep_kernel<<<8, 128>>>(cb);
    vq_kernel<<<NBLOCKS, THREADS, SMEM_TOTAL>>>(z, cb, out);
    if (out_size > ZELEMS)
        loss_kernel<<<1, 512>>>(out + ZELEMS);
}

// round 9
// speedup vs baseline: 2.3613x; 1.0980x over previous
#include <cuda_runtime.h>
#include <cuda_bf16.h>
#include <cstdint>

// Problem constants (z: [32,64,64,64] f32, codebook: [1024,64] f32)
#define BB      32
#define CC      64
#define HWN     4096
#define NQ      (BB * HWN)        // 131072 queries
#define KCODES  1024
#define MTILE   128               // queries per CTA
#define NCHUNK  128               // codes staged per smem chunk
#define NCH     (KCODES / NCHUNK) // 8
#define THREADS 128
#define NBLOCKS (NQ / MTILE)      // 1024
#define ZELEMS  (BB * CC * HWN)
#define EPS_SCREEN 0.75f          // hi-only screening window (worst-case bf16 bound)
#define EPS_TIE    5e-3f          // fp32 diff-form tie gate (>>2e-5 error bound)
#define PADW    72                // row stride (bf16): 144B = 9*16B, ldmatrix conflict-free

#define BBYTES  (NCHUNK * PADW * 2)            // 18432 per chunk image
#define OFF_BUF0   0
#define OFF_BUF1   (BBYTES + 512)              // 18944
#define OFF_SCN0   BBYTES
#define OFF_SCN1   (OFF_BUF1 + BBYTES)
#define OFF_WERR   (OFF_BUF1 + BBYTES + 512)   // 37888
#define SMEM_TOTAL (OFF_WERR + 64)             // 37952

__device__ float g_cnorm[KCODES];
__device__ float g_partials[NBLOCKS];
// prepped codebook: bf16 of (-2c), rows padded to PADW
__device__ __align__(16) __nv_bfloat16 g_cbimg[KCODES * PADW];

// ---------------------------------------------------------------------------
__device__ __forceinline__ uint32_t smem_to_u32(const void* p) {
    uint32_t a;
    asm("{ .reg .u64 t; cvta.to.shared.u64 t, %1; cvt.u32.u64 %0, t; }"
        : "=r"(a) : "l"(p));
    return a;
}

#define LDSM_X4(r, addr) \
    asm volatile("ldmatrix.sync.aligned.m8n8.x4.shared.b16 {%0,%1,%2,%3}, [%4];" \
        : "=r"((r)[0]), "=r"((r)[1]), "=r"((r)[2]), "=r"((r)[3]) : "r"(addr))

#define MMA16816(d, a, b) \
    asm volatile("mma.sync.aligned.m16n8k16.row.col.f32.bf16.bf16.f32 " \
        "{%0,%1,%2,%3}, {%4,%5,%6,%7}, {%8,%9}, {%0,%1,%2,%3};" \
        : "+f"((d)[0]), "+f"((d)[1]), "+f"((d)[2]), "+f"((d)[3]) \
        : "r"((a)[0]), "r"((a)[1]), "r"((a)[2]), "r"((a)[3]), \
          "r"((b)[0]), "r"((b)[1]))

#define CP_ASYNC16(sm, gp) \
    asm volatile("cp.async.cg.shared.global [%0], [%1], 16;" :: "r"(sm), "l"(gp))
#define CP_ASYNC4(sm, gp) \
    asm volatile("cp.async.ca.shared.global [%0], [%1], 4;" :: "r"(sm), "l"(gp))
#define CP_COMMIT() asm volatile("cp.async.commit_group;" ::: "memory")
#define CP_WAIT1()  asm volatile("cp.async.wait_group 1;" ::: "memory")

__device__ __forceinline__ void top4_insert(float s, int idx, float* ts, int* ti) {
    if (s < ts[3]) {
        if (s < ts[0]) {
            ts[3]=ts[2]; ti[3]=ti[2]; ts[2]=ts[1]; ti[2]=ti[1];
            ts[1]=ts[0]; ti[1]=ti[0]; ts[0]=s; ti[0]=idx;
        } else if (s < ts[1]) {
            ts[3]=ts[2]; ti[3]=ti[2]; ts[2]=ts[1]; ti[2]=ti[1]; ts[1]=s; ti[1]=idx;
        } else if (s < ts[2]) {
            ts[3]=ts[2]; ti[3]=ti[2]; ts[2]=s; ti[2]=idx;
        } else {
            ts[3]=s; ti[3]=idx;
        }
    }
}

// ---------------------------------------------------------------------------
// Kernel 0: prep — cn = ||c||^2 (fp32 exact), bf16 image of (-2c)
// ---------------------------------------------------------------------------
__global__ void prep_kernel(const float* __restrict__ cb) {
    int k = blockIdx.x * blockDim.x + threadIdx.x;
    if (k >= KCODES) return;
    const float2* r = reinterpret_cast<const float2*>(cb + (size_t)k * CC);
    __nv_bfloat16* row = g_cbimg + (size_t)k * PADW;
    float cn = 0.f;
#pragma unroll
    for (int c = 0; c < CC / 2; c++) {
        float2 v = __ldg(r + c);
        cn = fmaf(v.x, v.x, cn);
        cn = fmaf(v.y, v.y, cn);
        __nv_bfloat162 hp;
        hp.x = __float2bfloat16_rn(-2.f * v.x);
        hp.y = __float2bfloat16_rn(-2.f * v.y);
        *reinterpret_cast<__nv_bfloat162*>(row + 2 * c) = hp;
    }
    g_cnorm[k] = cn;
}

// fp64 exact squared distance (tier-2, rare)
__device__ double dist2_f64(const float* __restrict__ zp,
                            const float* __restrict__ cb, int idx) {
    const float* cp = cb + (size_t)idx * CC;
    double d = 0.0;
#pragma unroll
    for (int c = 0; c < CC; c++) {
        double df = (double)zp[(size_t)c * HWN] - (double)__ldg(cp + c);
        d = fma(df, df, d);
    }
    return d;
}

// ---------------------------------------------------------------------------
// Kernel 1: HMMA VQ — hi-only bf16 screen + two-tier exact refinement
// ---------------------------------------------------------------------------
extern __shared__ unsigned char dynsmem[];

__global__ __launch_bounds__(THREADS, 4)
void vq_kernel(const float* __restrict__ z,
               const float* __restrict__ cb,
               float* __restrict__ out) {
    const int tid = threadIdx.x;
    const int w = tid >> 5;
    const int l = tid & 31;
    const uint32_t sb = smem_to_u32(dynsmem);

    __nv_bfloat16* Ahi = reinterpret_cast<__nv_bfloat16*>(dynsmem + OFF_BUF0);
    float* werr = reinterpret_cast<float*>(dynsmem + OFF_WERR);
    float2* cand = reinterpret_cast<float2*>(dynsmem + OFF_BUF0);  // post-loop

    const int q = blockIdx.x * MTILE + tid;
    const int b = q >> 12;
    const float* zp = z + (size_t)b * CC * HWN + (q & (HWN - 1));

    // --- A tile: z query -> bf16 hi, staged transiently in buf0.B ---
#pragma unroll
    for (int c = 0; c < CC; c++)
        Ahi[tid * PADW + c] = __float2bfloat16_rn(zp[(size_t)c * HWN]);
    __syncthreads();

    // --- hoist A fragments: 4 k-slices x (a0[4], a1[4]) = 32 regs ---
    const int rowA = w * 32 + (l & 15);
    const int colA = ((l >> 4) & 1) * 8;
    uint32_t afr[32];
#pragma unroll
    for (int fi = 0; fi < 4; fi++) {
        LDSM_X4(afr + fi * 8,
                sb + OFF_BUF0 + (uint32_t)((rowA)      * PADW + colA + fi * 16) * 2);
        LDSM_X4(afr + fi * 8 + 4,
                sb + OFF_BUF0 + (uint32_t)((rowA + 16) * PADW + colA + fi * 16) * 2);
    }
    __syncthreads();   // buf0 free for prefetch

    // --- prefetch chunks 0,1 via cp.async (double buffer) ---
    const uint32_t bufB[2]   = { sb + OFF_BUF0, sb + OFF_BUF1 };
    const uint32_t bufSCN[2] = { sb + OFF_SCN0, sb + OFF_SCN1 };
#pragma unroll
    for (int p = 0; p < 2; p++) {
        const char* src = reinterpret_cast<const char*>(g_cbimg) + (size_t)p * BBYTES;
#pragma unroll
        for (int i = 0; i < 9; i++)
            CP_ASYNC16(bufB[p] + (uint32_t)(tid + i * THREADS) * 16,
                       src + (size_t)(tid + i * THREADS) * 16);
        CP_ASYNC4(bufSCN[p] + (uint32_t)tid * 4,
                  reinterpret_cast<const char*>(g_cnorm) + (size_t)(p * NCHUNK + tid) * 4);
        CP_COMMIT();
    }

    // per-thread top-4 over 4 query-slots (16 disjoint code-subsets)
    float ts[16];
    int   ti[16];
#pragma unroll
    for (int i = 0; i < 16; i++) { ts[i] = 3.4e38f; ti[i] = 0x7fffffff; }

    const int rowB = ((l >> 4) & 1) * 8 + (l & 7);
    const int colB = ((l >> 3) & 1) * 8;

#pragma unroll 1
    for (int ch = 0; ch < NCH; ch++) {
        CP_WAIT1();
        __syncthreads();

        const uint32_t Bc = bufB[ch & 1];
        const float* scn = reinterpret_cast<const float*>(
            dynsmem + (((ch & 1) ? OFF_SCN1 : OFF_SCN0)));

#pragma unroll 1
        for (int nsub = 0; nsub < 4; nsub++) {
            float d[32];
#pragma unroll
            for (int nt = 0; nt < 4; nt++) {
                float cn0 = scn[nsub * 32 + nt * 8 + 2 * (l & 3)];
                float cn1 = scn[nsub * 32 + nt * 8 + 2 * (l & 3) + 1];
#pragma unroll
                for (int mt = 0; mt < 2; mt++) {
                    d[(mt * 4 + nt) * 4 + 0] = cn0;
                    d[(mt * 4 + nt) * 4 + 1] = cn1;
                    d[(mt * 4 + nt) * 4 + 2] = cn0;
                    d[(mt * 4 + nt) * 4 + 3] = cn1;
                }
            }

            const uint32_t bbase = Bc + (uint32_t)((nsub * 32 + rowB) * PADW + colB) * 2;

            // hi-only screen: zh * bh (4 k-steps)
#pragma unroll
            for (int s = 0; s < 4; s++) {
                uint32_t bf[8];
                LDSM_X4(bf,     bbase + (uint32_t)(s * 16) * 2);
                LDSM_X4(bf + 4, bbase + (uint32_t)(16 * PADW + s * 16) * 2);
                const uint32_t* a0 = afr + s * 8;
#pragma unroll
                for (int nt = 0; nt < 4; nt++) {
                    MMA16816(d + (0 * 4 + nt) * 4, a0,     bf + nt * 2);
                    MMA16816(d + (1 * 4 + nt) * 4, a0 + 4, bf + nt * 2);
                }
            }

#pragma unroll
            for (int mt = 0; mt < 2; mt++)
#pragma unroll
                for (int nt = 0; nt < 4; nt++)
#pragma unroll
                    for (int e = 0; e < 4; e++) {
                        float s = d[(mt * 4 + nt) * 4 + e];
                        int idx = ch * NCHUNK + nsub * 32 + nt * 8 + 2 * (l & 3) + (e & 1);
                        int slot = mt * 2 + (e >> 1);
                        top4_insert(s, idx, ts + slot * 4, ti + slot * 4);
                    }
        }

        __syncthreads();
        if (ch + 2 < NCH) {
            const char* src = reinterpret_cast<const char*>(g_cbimg) + (size_t)(ch + 2) * BBYTES;
#pragma unroll
            for (int i = 0; i < 9; i++)
                CP_ASYNC16(bufB[ch & 1] + (uint32_t)(tid + i * THREADS) * 16,
                           src + (size_t)(tid + i * THREADS) * 16);
            CP_ASYNC4(bufSCN[ch & 1] + (uint32_t)tid * 4,
                      reinterpret_cast<const char*>(g_cnorm) + (size_t)((ch + 2) * NCHUNK + tid) * 4);
            CP_COMMIT();
        }
    }

    // --- merge candidates via smem (stride 17 float2; reuses buf0) ---
#pragma unroll
    for (int s = 0; s < 4; s++) {
        int mt = s >> 1, half = s & 1;
        int ql = w * 32 + mt * 16 + half * 8 + (l >> 2);
#pragma unroll
        for (int e = 0; e < 4; e++)
            cand[ql * 17 + (l & 3) * 4 + e] =
                make_float2(ts[s * 4 + e], __int_as_float(ti[s * 4 + e]));
    }
    __syncthreads();

    // --- per-query (thread = query): window + two-tier refinement ---
    float cs[16]; int ci[16];
#pragma unroll
    for (int j = 0; j < 16; j++) {
        float2 v = cand[tid * 17 + j];
        cs[j] = v.x; ci[j] = __float_as_int(v.y);
    }
    float smin = cs[0];
#pragma unroll
    for (int j = 1; j < 16; j++) smin = fminf(smin, cs[j]);

    int nwin = 0, lone = 0;
#pragma unroll
    for (int j = 0; j < 16; j++)
        if (cs[j] < smin + EPS_SCREEN) { nwin++; lone = j; }

    int bidx;
    if (nwin == 1) {
        bidx = ci[lone];
    } else {
        // compact window candidate indices
        int wc[16]; int nw = 0;
#pragma unroll
        for (int j = 0; j < 16; j++)
            if (cs[j] < smin + EPS_SCREEN) wc[nw++] = ci[j];

        // tier 1: fp32 diff-form, two candidates per pass (z loads shared,
        // codebook rows as float4, 8 independent FMA chains)
        float dv[16];
        float best = 3.4e38f;
        int   bi = 0x7fffffff;
#pragma unroll 1
        for (int j0 = 0; j0 < nw; j0 += 2) {
            int iA = wc[j0];
            int iB = wc[(j0 + 1 < nw) ? (j0 + 1) : j0];
            const float4* pA = reinterpret_cast<const float4*>(cb + (size_t)iA * CC);
            const float4* pB = reinterpret_cast<const float4*>(cb + (size_t)iB * CC);
            float dA0 = 0.f, dA1 = 0.f, dB0 = 0.f, dB1 = 0.f;
#pragma unroll
            for (int c = 0; c < CC / 4; c++) {
                float4 a4 = __ldg(pA + c);
                float4 b4 = __ldg(pB + c);
                float z0 = zp[(size_t)(4 * c + 0) * HWN];
                float z1 = zp[(size_t)(4 * c + 1) * HWN];
                float z2 = zp[(size_t)(4 * c + 2) * HWN];
                float z3 = zp[(size_t)(4 * c + 3) * HWN];
                float tA0 = z0 - a4.x, tA1 = z1 - a4.y, tA2 = z2 - a4.z, tA3 = z3 - a4.w;
                float tB0 = z0 - b4.x, tB1 = z1 - b4.y, tB2 = z2 - b4.z, tB3 = z3 - b4.w;
                dA0 = fmaf(tA0, tA0, dA0); dA1 = fmaf(tA1, tA1, dA1);
                dA0 = fmaf(tA2, tA2, dA0); dA1 = fmaf(tA3, tA3, dA1);
                dB0 = fmaf(tB0, tB0, dB0); dB1 = fmaf(tB1, tB1, dB1);
                dB0 = fmaf(tB2, tB2, dB0); dB1 = fmaf(tB3, tB3, dB1);
            }
            float dA = dA0 + dA1;
            float dB = dB0 + dB1;
            dv[j0] = dA;
            if (dA < best || (dA == best && iA < bi)) { best = dA; bi = iA; }
            if (j0 + 1 < nw) {
                dv[j0 + 1] = dB;
                if (dB < best || (dB == best && iB < bi)) { best = dB; bi = iB; }
            }
        }

        // tier 2: fp64 only on fp32 near-ties (rare)
        int ntie = 0;
#pragma unroll 1
        for (int j = 0; j < nw; j++)
            if (dv[j] < best + EPS_TIE) ntie++;
        if (ntie > 1) {
            double bd = 1e300;
            int bi64 = 0x7fffffff;
#pragma unroll 1
            for (int j = 0; j < nw; j++) {
                if (dv[j] < best + EPS_TIE) {
                    double dd = dist2_f64(zp, cb, wc[j]);
                    if (dd < bd || (dd == bd && wc[j] < bi64)) { bd = dd; bi64 = wc[j]; }
                }
            }
            bi = bi64;
        }
        bidx = bi;
    }

    // --- write z_q + squared-error partial (coalesced; cb row as float4) ---
    float err = 0.f;
    {
        const float4* cv4 = reinterpret_cast<const float4*>(cb + (size_t)bidx * CC);
        float* op = out + (size_t)b * CC * HWN + (q & (HWN - 1));
#pragma unroll
        for (int i = 0; i < CC / 4; i++) {
            float4 v = __ldg(cv4 + i);
            float z0 = zp[(size_t)(4 * i + 0) * HWN];
            float z1 = zp[(size_t)(4 * i + 1) * HWN];
            float z2 = zp[(size_t)(4 * i + 2) * HWN];
            float z3 = zp[(size_t)(4 * i + 3) * HWN];
            op[(size_t)(4 * i + 0) * HWN] = v.x;
            op[(size_t)(4 * i + 1) * HWN] = v.y;
            op[(size_t)(4 * i + 2) * HWN] = v.z;
            op[(size_t)(4 * i + 3) * HWN] = v.w;
            float d0 = v.x - z0, d1 = v.y - z1, d2 = v.z - z2, d3 = v.w - z3;
            err = fmaf(d0, d0, err);
            err = fmaf(d1, d1, err);
            err = fmaf(d2, d2, err);
            err = fmaf(d3, d3, err);
        }
    }
#pragma unroll
    for (int o = 16; o > 0; o >>= 1)
        err += __shfl_down_sync(0xFFFFFFFFu, err, o);
    if (l == 0) werr[w] = err;
    __syncthreads();
    if (tid == 0)
        g_partials[blockIdx.x] = werr[0] + werr[1] + werr[2] + werr[3];
}

// ---------------------------------------------------------------------------
// Kernel 2: deterministic loss = 1.25 * mean((z_q - z)^2)
// ---------------------------------------------------------------------------
__global__ void loss_kernel(float* __restrict__ loss_out) {
    __shared__ double s[512];
    s[threadIdx.x] = (double)g_partials[threadIdx.x] +
                     (double)g_partials[threadIdx.x + 512];
    __syncthreads();
#pragma unroll
    for (int st = 256; st > 0; st >>= 1) {
        if (threadIdx.x < st) s[threadIdx.x] += s[threadIdx.x + st];
        __syncthreads();
    }
    if (threadIdx.x == 0)
        loss_out[0] = (float)(1.25 * s[0] / (double)ZELEMS);
}

// ---------------------------------------------------------------------------
extern "C" void kernel_launch(void* const* d_in, const int* in_sizes, int n_in,
                              void* d_out, int out_size) {
    const float* z  = (const float*)d_in[0];
    const float* cb = (const float*)d_in[1];
    float* out = (float*)d_out;

    cudaFuncSetAttribute(vq_kernel, cudaFuncAttributeMaxDynamicSharedMemorySize,
                         SMEM_TOTAL);

    prep_kernel<<<8, 128>>>(cb);
    vq_kernel<<<NBLOCKS, THREADS, SMEM_TOTAL>>>(z, cb, out);
    if (out_size > ZELEMS)
        loss_kernel<<<1, 512>>>(out + ZELEMS);
}